// round 6
// baseline (speedup 1.0000x reference)
#include <cuda_runtime.h>
#include <cuda.h>
#include <cuda_bf16.h>
#include <cstdint>
#include <cstring>

// ConsistencyLoss: B=8192, E=16, H=1024
// Round 6: mma.sync bf16 128x128 Gram tiles, TMA (cp.async.bulk.tensor.2d)
// 3-stage ring + mbarrier, 2 CTAs/SM, fused masked-KL epilogue.
// Fallback to validated R5 cp.async pipeline if driver entry point missing.

#define BDIM 8192
#define HDIM 1024
#define EDIM 16
#define TILE 128
#define NT   (BDIM / TILE)            // 64
#define NBLK (NT * (NT + 1) / 2)      // 2080
#define SIM_THR 0.8f

#define KSTAGE 64                     // bf16 K-cols per stage (128 B/row)
#define NSTAGE (HDIM / KSTAGE)        // 16
#define STAGE_B 32768                 // A 16K + B 16K

// dynamic smem: 1KB ctrl + 1KB align slack + 3 stages
#define SM_ALLOC (1024 + 1024 + 3 * STAGE_B)   // 100352 -> 2 CTAs = 196.5KB

__device__ __nv_bfloat16 g_embn[BDIM * HDIM];
__device__ float  g_L[BDIM * EDIM];
__device__ float  g_P[BDIM * EDIM];
__device__ float  g_ne[BDIM];
__device__ double g_sum;
__device__ unsigned long long g_cnt;

__device__ __forceinline__ uint32_t smem_u32(const void* p) {
    uint32_t a;
    asm("{ .reg .u64 t; cvta.to.shared.u64 t, %1; cvt.u32.u64 %0, t; }" : "=r"(a) : "l"(p));
    return a;
}

#define MBAR_INIT(addr, cnt) \
    asm volatile("mbarrier.init.shared.b64 [%0], %1;" :: "r"(addr), "r"(cnt) : "memory")
#define MBAR_EXPECT_TX(addr, bytes) \
    asm volatile("mbarrier.arrive.expect_tx.shared.b64 _, [%0], %1;" \
                 :: "r"(addr), "r"((uint32_t)(bytes)) : "memory")
#define MBAR_WAIT(addr, parity) do {                                           \
    uint32_t _m = (addr), _p = (parity), _done;                                \
    asm volatile("{\n\t.reg .pred p;\n\t"                                      \
        "mbarrier.try_wait.parity.acquire.cta.shared::cta.b64 p, [%1], %2;\n\t"\
        "selp.b32 %0, 1, 0, p;\n\t}" : "=r"(_done) : "r"(_m), "r"(_p) : "memory"); \
    if (!_done) {                                                              \
        asm volatile("{\n\t.reg .pred P1;\n\t"                                 \
            "WL_%=:\n\t"                                                       \
            "mbarrier.try_wait.parity.acquire.cta.shared::cta.b64 P1, [%0], %1, 0x989680;\n\t" \
            "@P1 bra.uni WD_%=;\n\t"                                           \
            "bra.uni WL_%=;\n\t"                                               \
            "WD_%=:\n\t}" :: "r"(_m), "r"(_p) : "memory");                     \
    }                                                                          \
} while (0)

#define CPASYNC16(sa, gp) \
    asm volatile("cp.async.cg.shared.global [%0], [%1], 16;" :: "r"(sa), "l"(gp) : "memory")
#define CP_COMMIT() asm volatile("cp.async.commit_group;" ::: "memory")
#define CP_WAIT2() asm volatile("cp.async.wait_group 2;" ::: "memory")
#define CP_WAIT0() asm volatile("cp.async.wait_group 0;" ::: "memory")

__device__ __forceinline__ void tma_load_2d(const CUtensorMap* m, uint32_t dst,
                                            int x, int y, uint32_t bar) {
    asm volatile(
        "cp.async.bulk.tensor.2d.shared::cta.global.tile.mbarrier::complete_tx::bytes "
        "[%0], [%1, {%2, %3}], [%4];"
        :: "r"(dst), "l"(m), "r"(x), "r"(y), "r"(bar) : "memory");
}

// ---------------- prep kernels ----------------
__global__ void init_kernel() { g_sum = 0.0; g_cnt = 0ull; }

__global__ void normalize_kernel(const float* __restrict__ emb) {
    int row = blockIdx.x;
    int t = threadIdx.x;
    float4 v = reinterpret_cast<const float4*>(emb + (size_t)row * HDIM)[t];
    float ss = v.x * v.x + v.y * v.y + v.z * v.z + v.w * v.w;
    #pragma unroll
    for (int o = 16; o > 0; o >>= 1) ss += __shfl_down_sync(0xffffffffu, ss, o);
    __shared__ float red[8];
    int lane = t & 31, w = t >> 5;
    if (lane == 0) red[w] = ss;
    __syncthreads();
    if (t < 32) {
        float s = (t < 8) ? red[t] : 0.f;
        #pragma unroll
        for (int o = 4; o > 0; o >>= 1) s += __shfl_down_sync(0xffffffffu, s, o);
        if (t == 0) red[0] = s;
    }
    __syncthreads();
    float inv = rsqrtf(red[0]);
    __nv_bfloat162 h0 = __floats2bfloat162_rn(v.x * inv, v.y * inv);
    __nv_bfloat162 h1 = __floats2bfloat162_rn(v.z * inv, v.w * inv);
    uint2 o2;
    *reinterpret_cast<__nv_bfloat162*>(&o2.x) = h0;
    *reinterpret_cast<__nv_bfloat162*>(&o2.y) = h1;
    reinterpret_cast<uint2*>(g_embn + (size_t)row * HDIM)[t] = o2;
}

__global__ void routing_kernel(const float* __restrict__ rp) {
    int row = blockIdx.x * blockDim.x + threadIdx.x;
    if (row >= BDIM) return;
    float x[EDIM];
    float m = -1e30f;
    #pragma unroll
    for (int e = 0; e < EDIM; e++) { x[e] = rp[row * EDIM + e]; m = fmaxf(m, x[e]); }
    float s = 0.f;
    #pragma unroll
    for (int e = 0; e < EDIM; e++) s += expf(x[e] - m);
    float lse = m + logf(s);
    float ne = 0.f;
    #pragma unroll
    for (int e = 0; e < EDIM; e++) {
        float L = x[e] - lse;
        float P = expf(L);
        g_L[row * EDIM + e] = L;
        g_P[row * EDIM + e] = P;
        ne = fmaf(P, L, ne);
    }
    g_ne[row] = ne;
}

// ---------------- shared compute body ----------------
__device__ __forceinline__ void compute_stage(uint32_t sA, uint32_t sB,
                                              int wm, int wn, int lane,
                                              float acc[4][4][4]) {
    #pragma unroll
    for (int kk = 0; kk < 4; kk++) {
        uint32_t bf[4][2];
        #pragma unroll
        for (int g = 0; g < 4; g++) {
            int row = wn * 32 + g * 8 + (lane & 7);
            int ch = (kk * 2 + ((lane >> 3) & 1)) ^ (row & 7);
            uint32_t addr = sB + (uint32_t)row * 128 + ch * 16;
            asm volatile("ldmatrix.sync.aligned.m8n8.x2.shared.b16 {%0,%1}, [%2];"
                : "=r"(bf[g][0]), "=r"(bf[g][1]) : "r"(addr));
        }
        uint32_t a[4][4];
        #pragma unroll
        for (int f = 0; f < 4; f++) {
            int arow = wm * 64 + f * 16 + (lane & 15);
            int ach = (kk * 2 + (lane >> 4)) ^ (arow & 7);
            uint32_t addr = sA + (uint32_t)arow * 128 + ach * 16;
            asm volatile("ldmatrix.sync.aligned.m8n8.x4.shared.b16 {%0,%1,%2,%3}, [%4];"
                : "=r"(a[f][0]), "=r"(a[f][1]), "=r"(a[f][2]), "=r"(a[f][3]) : "r"(addr));
        }
        #pragma unroll
        for (int f = 0; f < 4; f++)
            #pragma unroll
            for (int g = 0; g < 4; g++)
                asm volatile(
                    "mma.sync.aligned.m16n8k16.row.col.f32.bf16.bf16.f32 "
                    "{%0,%1,%2,%3}, {%4,%5,%6,%7}, {%8,%9}, {%0,%1,%2,%3};"
                    : "+f"(acc[f][g][0]), "+f"(acc[f][g][1]),
                      "+f"(acc[f][g][2]), "+f"(acc[f][g][3])
                    : "r"(a[f][0]), "r"(a[f][1]), "r"(a[f][2]), "r"(a[f][3]),
                      "r"(bf[g][0]), "r"(bf[g][1]));
    }
}

// ---------------- main fused kernel ----------------
__global__ __launch_bounds__(256, 2) void main_kernel(
    const __grid_constant__ CUtensorMap tmap, int use_tma) {
    extern __shared__ char smem[];
    uint32_t sb = smem_u32(smem);
    uint32_t ab = (sb + 1024 + 1023) & ~1023u;   // 1024-aligned stage base
    char* stg = smem + (ab - sb);
    int tid = threadIdx.x;
    int wid = tid >> 5, lane = tid & 31;
    const int wm = wid >> 2, wn = wid & 3;

    // block -> (ti, tj), tj >= ti
    int ti = 0, rem = blockIdx.x;
    while (rem >= NT - ti) { rem -= NT - ti; ti++; }
    int tj = ti + rem;
    bool diag = (ti == tj);

    float acc[4][4][4];
    #pragma unroll
    for (int f = 0; f < 4; f++)
        #pragma unroll
        for (int g = 0; g < 4; g++)
            #pragma unroll
            for (int r = 0; r < 4; r++) acc[f][g][r] = 0.f;

    if (use_tma) {
        // ---- TMA path: 1 elected producer, mbarrier ring ----
        if (tid == 0) {
            MBAR_INIT(sb + 0, 1);
            MBAR_INIT(sb + 8, 1);
            MBAR_INIT(sb + 16, 1);
        }
        __syncthreads();
        if (tid == 0) {
            #pragma unroll
            for (int s = 0; s < 3; s++) {
                uint32_t bar = sb + s * 8;
                MBAR_EXPECT_TX(bar, STAGE_B);
                tma_load_2d(&tmap, ab + s * STAGE_B,         s * KSTAGE, ti * TILE, bar);
                tma_load_2d(&tmap, ab + s * STAGE_B + 16384, s * KSTAGE, tj * TILE, bar);
            }
        }
        for (int s = 0; s < NSTAGE; s++) {
            int slot = s - (s / 3) * 3;
            int ph = (s / 3) & 1;
            MBAR_WAIT(sb + slot * 8, ph);
            compute_stage(ab + slot * STAGE_B, ab + slot * STAGE_B + 16384,
                          wm, wn, lane, acc);
            __syncthreads();
            if (tid == 0 && s + 3 < NSTAGE) {
                uint32_t bar = sb + slot * 8;
                MBAR_EXPECT_TX(bar, STAGE_B);
                tma_load_2d(&tmap, ab + slot * STAGE_B,         (s + 3) * KSTAGE, ti * TILE, bar);
                tma_load_2d(&tmap, ab + slot * STAGE_B + 16384, (s + 3) * KSTAGE, tj * TILE, bar);
            }
        }
    } else {
        // ---- fallback: validated R5 cp.async pipeline ----
        const int crow = tid >> 1;
        const int cq0 = (tid & 1) * 4;
        const __nv_bfloat16* Abase = g_embn + (size_t)(ti * TILE + crow) * HDIM;
        const __nv_bfloat16* Bbase = g_embn + (size_t)(tj * TILE + crow) * HDIM;

        #define COPY_STAGE(buf, s) do {                                           \
            uint32_t sA = ab + (buf) * STAGE_B;                                   \
            uint32_t sB = sA + 16384;                                             \
            int k0 = (s) * KSTAGE;                                                \
            _Pragma("unroll")                                                     \
            for (int q = 0; q < 4; q++) {                                         \
                int qq = cq0 + q;                                                 \
                uint32_t soff = crow * 128 + ((qq ^ (crow & 7)) * 16);            \
                CPASYNC16(sA + soff, Abase + k0 + qq * 8);                        \
                CPASYNC16(sB + soff, Bbase + k0 + qq * 8);                        \
            }                                                                     \
        } while (0)

        COPY_STAGE(0, 0); CP_COMMIT();
        COPY_STAGE(1, 1); CP_COMMIT();
        COPY_STAGE(2, 2); CP_COMMIT();

        for (int s = 0; s < NSTAGE; s++) {
            int buf = s - (s / 3) * 3;
            CP_WAIT2();
            __syncthreads();
            compute_stage(ab + buf * STAGE_B, ab + buf * STAGE_B + 16384,
                          wm, wn, lane, acc);
            __syncthreads();
            if (s + 3 < NSTAGE) { COPY_STAGE(buf, s + 3); }
            CP_COMMIT();
        }
        CP_WAIT0();
        __syncthreads();
    }

    // ---- stage L/P/ne for row block and col block (reuses stage region) ----
    {
        float4* Lr4 = reinterpret_cast<float4*>(stg);
        float4* Pr4 = reinterpret_cast<float4*>(stg + 8192);
        float4* Lc4 = reinterpret_cast<float4*>(stg + 16384);
        float4* Pc4 = reinterpret_cast<float4*>(stg + 24576);
        const float4* GLr = reinterpret_cast<const float4*>(g_L) + (size_t)ti * TILE * 4;
        const float4* GPr = reinterpret_cast<const float4*>(g_P) + (size_t)ti * TILE * 4;
        const float4* GLc = reinterpret_cast<const float4*>(g_L) + (size_t)tj * TILE * 4;
        const float4* GPc = reinterpret_cast<const float4*>(g_P) + (size_t)tj * TILE * 4;
        for (int s = tid; s < 512; s += 256) {
            Lr4[s] = GLr[s]; Pr4[s] = GPr[s]; Lc4[s] = GLc[s]; Pc4[s] = GPc[s];
        }
        float* nr = reinterpret_cast<float*>(stg + 32768);
        float* nc = reinterpret_cast<float*>(stg + 32768 + 512);
        if (tid < 128) { nr[tid] = g_ne[ti * TILE + tid]; nc[tid] = g_ne[tj * TILE + tid]; }
    }
    __syncthreads();

    float sumv = 0.f;
    unsigned int cntv = 0;
    {
        const float* Lr = reinterpret_cast<const float*>(stg);
        const float* Pr = reinterpret_cast<const float*>(stg + 8192);
        const float* Lc = reinterpret_cast<const float*>(stg + 16384);
        const float* Pc = reinterpret_cast<const float*>(stg + 24576);
        const float* nr = reinterpret_cast<const float*>(stg + 32768);
        const float* nc = reinterpret_cast<const float*>(stg + 32768 + 512);
        int t4 = lane >> 2, t2 = (lane & 3) * 2;
        #pragma unroll
        for (int f = 0; f < 4; f++)
            #pragma unroll
            for (int g = 0; g < 4; g++)
                #pragma unroll
                for (int r = 0; r < 4; r++) {
                    float s = acc[f][g][r];
                    int i = wm * 64 + f * 16 + t4 + (r >> 1) * 8;
                    int j = wn * 32 + g * 8 + t2 + (r & 1);
                    if (s > SIM_THR && (!diag || i != j)) {
                        float d1 = 0.f;
                        #pragma unroll
                        for (int e = 0; e < EDIM; e++)
                            d1 = fmaf(Lr[i * 16 + e], Pc[j * 16 + e], d1);
                        float klij = nc[j] - d1;
                        if (diag) { sumv += klij; cntv += 1u; }
                        else {
                            float d2 = 0.f;
                            #pragma unroll
                            for (int e = 0; e < EDIM; e++)
                                d2 = fmaf(Lc[j * 16 + e], Pr[i * 16 + e], d2);
                            sumv += klij + (nr[i] - d2);
                            cntv += 2u;
                        }
                    }
                }
    }

    // block reduce + single atomic
    #pragma unroll
    for (int o = 16; o > 0; o >>= 1) {
        sumv += __shfl_down_sync(0xffffffffu, sumv, o);
        cntv += __shfl_down_sync(0xffffffffu, cntv, o);
    }
    float* rs = reinterpret_cast<float*>(smem + 64);
    unsigned int* rc = reinterpret_cast<unsigned int*>(smem + 96);
    if (lane == 0) { rs[wid] = sumv; rc[wid] = cntv; }
    __syncthreads();
    if (tid == 0) {
        float ts = 0.f; unsigned int tc = 0;
        #pragma unroll
        for (int q = 0; q < 8; q++) { ts += rs[q]; tc += rc[q]; }
        if (tc > 0) {
            atomicAdd(&g_sum, (double)ts);
            atomicAdd(&g_cnt, (unsigned long long)tc);
        }
    }
}

__global__ void finalize_kernel(float* __restrict__ out) {
    unsigned long long c = g_cnt;
    out[0] = (c > 0) ? (float)(g_sum / (double)c) : 0.0f;   // WEIGHT = 1.0
}

// ---------------- host ----------------
typedef CUresult (*PFN_tmap_encode)(
    CUtensorMap*, CUtensorMapDataType, cuuint32_t, void*,
    const cuuint64_t*, const cuuint64_t*, const cuuint32_t*, const cuuint32_t*,
    CUtensorMapInterleave, CUtensorMapSwizzle, CUtensorMapL2promotion,
    CUtensorMapFloatOOBfill);

extern "C" void kernel_launch(void* const* d_in, const int* in_sizes, int n_in,
                              void* d_out, int out_size) {
    const float* rp;
    const float* emb;
    if (in_sizes[0] == BDIM * EDIM) {
        rp = (const float*)d_in[0];
        emb = (const float*)d_in[1];
    } else {
        rp = (const float*)d_in[1];
        emb = (const float*)d_in[0];
    }
    float* out = (float*)d_out;

    static int inited = 0;
    static PFN_tmap_encode s_encode = nullptr;
    static void* s_embn_dev = nullptr;
    if (!inited) {
        inited = 1;
        cudaFuncSetAttribute(main_kernel,
                             cudaFuncAttributeMaxDynamicSharedMemorySize, SM_ALLOC);
        void* fn = nullptr;
        cudaDriverEntryPointQueryResult qr;
        if (cudaGetDriverEntryPoint("cuTensorMapEncodeTiled", &fn,
                                    cudaEnableDefault, &qr) == cudaSuccess && fn)
            s_encode = (PFN_tmap_encode)fn;
        cudaGetSymbolAddress(&s_embn_dev, g_embn);
    }

    CUtensorMap tmap;
    memset(&tmap, 0, sizeof(tmap));
    int use_tma = 0;
    if (s_encode && s_embn_dev) {
        cuuint64_t dims[2]    = {HDIM, BDIM};
        cuuint64_t strides[1] = {HDIM * 2};
        cuuint32_t box[2]     = {KSTAGE, TILE};     // 64 bf16 = 128 B x 128 rows
        cuuint32_t es[2]      = {1, 1};
        CUresult r = s_encode(&tmap, CU_TENSOR_MAP_DATA_TYPE_UINT16, 2, s_embn_dev,
                              dims, strides, box, es,
                              CU_TENSOR_MAP_INTERLEAVE_NONE,
                              CU_TENSOR_MAP_SWIZZLE_128B,
                              CU_TENSOR_MAP_L2_PROMOTION_L2_128B,
                              CU_TENSOR_MAP_FLOAT_OOB_FILL_NONE);
        if (r == CUDA_SUCCESS) use_tma = 1;
    }

    init_kernel<<<1, 1>>>();
    normalize_kernel<<<BDIM, 256>>>(emb);
    routing_kernel<<<BDIM / 256, 256>>>(rp);
    main_kernel<<<NBLK, 256, SM_ALLOC>>>(tmap, use_tma);
    finalize_kernel<<<1, 1>>>(out);
}